// round 13
// baseline (speedup 1.0000x reference)
#include <cuda_runtime.h>
#include <cuda_bf16.h>
#include <math.h>
#include <stdint.h>

#define B 64
#define H 1024
#define T 1024
#define V 32000

#define S_GRU 4   // split-K for GRU gemms
#define S_CAT 16  // split-K for concat gemm
#define NCHUNK 8  // attention t-chunks (128 t each)

// ---------------- scratch (alloc-free: __device__ globals) ----------------
__device__ float g_emb[B * H];
__device__ float g_gxp[S_GRU * B * 3 * H];
__device__ float g_ghp[S_GRU * B * 3 * H];
__device__ float g_hnew[B * H];
__device__ float g_scores[B * T];
__device__ float g_pm[B * NCHUNK];
__device__ float g_ps[B * NCHUNK];
__device__ float g_ctxpart[B * NCHUNK * H];
__device__ float g_concat_in[B * 2 * H];
__device__ float g_cp[S_CAT * B * H];
__device__ __nv_bfloat16 g_xhi[B * H];
__device__ __nv_bfloat16 g_xlo[B * H];

typedef unsigned long long u64;

__device__ __forceinline__ u64 pack2(float lo, float hi) {
    u64 r;
    asm("mov.b64 %0, {%1, %2};" : "=l"(r) : "f"(lo), "f"(hi));
    return r;
}
__device__ __forceinline__ void unpack2(u64 v, float &lo, float &hi) {
    asm("mov.b64 {%0, %1}, %2;" : "=f"(lo), "=f"(hi) : "l"(v));
}
#define FMA2(d, a, b, c) \
    asm("fma.rn.f32x2 %0, %1, %2, %3;" : "=l"(d) : "l"(a), "l"(b), "l"(c))

#define SWZ(o) ((o) ^ ((((uint32_t)(o)) >> 3) & 0x70))

#define MMA16816(d, a0, a1, a2, a3, b0, b1)                             \
    asm volatile(                                                       \
        "mma.sync.aligned.m16n8k16.row.col.f32.bf16.bf16.f32 "          \
        "{%0,%1,%2,%3}, {%4,%5,%6,%7}, {%8,%9}, {%0,%1,%2,%3};"         \
        : "+f"((d)[0]), "+f"((d)[1]), "+f"((d)[2]), "+f"((d)[3])        \
        : "r"(a0), "r"(a1), "r"(a2), "r"(a3), "r"(b0), "r"(b1))

// ---------------------------------------------------------------------------
// Output GEMM via mma.sync bf16 (split precision), software-pipelined:
// W prefetch for chunk c+1 issued BEFORE the MMA phase of chunk c, so DRAM
// latency overlaps tensor work. B (xhi/xlo) is L2-resident, loaded in the
// convert phase. CTA: 128m x 64n, K chunks of 64; 8 warps of 32m x 32n.
// D = Whi.Xhi + Wlo.Xhi + Whi.Xlo (fp32 accumulate).
// ---------------------------------------------------------------------------
__global__ void __launch_bounds__(256, 2) out_gemm_mma(
    const float *__restrict__ W, const float *__restrict__ bias,
    float *__restrict__ Cout) {
    __shared__ __align__(16) __nv_bfloat16 sAhi[128 * 64];
    __shared__ __align__(16) __nv_bfloat16 sAlo[128 * 64];
    __shared__ __align__(16) __nv_bfloat16 sBhi[64 * 64];
    __shared__ __align__(16) __nv_bfloat16 sBlo[64 * 64];

    const int tid = threadIdx.x;
    const int lane = tid & 31;
    const int warp = tid >> 5;
    const int mBase = blockIdx.x * 128;

    const int warpM = (warp & 3) * 32;
    const int warpN = (warp >> 2) * 32;
    const int gid = lane >> 2;   // 0..7
    const int tig = lane & 3;    // 0..3

    const int rowA = tid >> 4;   // 0..15 (+16 per iter, 8 iters)
    const int kq = tid & 15;     // float4 within 64-k chunk
    const int rowB = tid >> 3;   // 0..31 (+32 per iter, 2 iters)
    const int qB = tid & 7;      // uint4 within 128B row

    float acc[2][4][4];
#pragma unroll
    for (int i = 0; i < 2; i++)
#pragma unroll
        for (int j = 0; j < 4; j++)
#pragma unroll
            for (int q = 0; q < 4; q++) acc[i][j][q] = 0.f;

    const char *cAhi = (const char *)sAhi;
    const char *cAlo = (const char *)sAlo;
    const char *cBhi = (const char *)sBhi;
    const char *cBlo = (const char *)sBlo;

    const float *Wp = W + (size_t)(mBase + rowA) * H + kq * 4;

    // prologue: W regs for chunk 0
    float4 wv[8];
#pragma unroll
    for (int it = 0; it < 8; ++it)
        wv[it] = *(const float4 *)(Wp + (size_t)it * 16 * H);

    for (int c = 0; c < 16; ++c) {
        const int k0 = c * 64;
        // ---- B loads (L2-resident after first CTA touches them) ----
        uint4 bh[2], bl[2];
#pragma unroll
        for (int it = 0; it < 2; ++it) {
            int r = rowB + it * 32;
            bh[it] = *(const uint4 *)(g_xhi + (size_t)r * H + k0 + qB * 8);
            bl[it] = *(const uint4 *)(g_xlo + (size_t)r * H + k0 + qB * 8);
        }
        __syncthreads();  // previous chunk fully consumed by MMA phase
        // ---- convert W regs -> bf16 hi/lo, store swizzled ----
#pragma unroll
        for (int it = 0; it < 8; ++it) {
            int r = rowA + it * 16;
            uint32_t off = SWZ((uint32_t)(r * 128 + kq * 8));
            __nv_bfloat162 h01 = __float22bfloat162_rn(make_float2(wv[it].x, wv[it].y));
            __nv_bfloat162 h23 = __float22bfloat162_rn(make_float2(wv[it].z, wv[it].w));
            float2 f01 = __bfloat1622float2(h01);
            float2 f23 = __bfloat1622float2(h23);
            __nv_bfloat162 l01 = __float22bfloat162_rn(
                make_float2(wv[it].x - f01.x, wv[it].y - f01.y));
            __nv_bfloat162 l23 = __float22bfloat162_rn(
                make_float2(wv[it].z - f23.x, wv[it].w - f23.y));
            *(uint2 *)((char *)sAhi + off) =
                make_uint2(*(uint32_t *)&h01, *(uint32_t *)&h23);
            *(uint2 *)((char *)sAlo + off) =
                make_uint2(*(uint32_t *)&l01, *(uint32_t *)&l23);
        }
#pragma unroll
        for (int it = 0; it < 2; ++it) {
            int r = rowB + it * 32;
            uint32_t off = SWZ((uint32_t)(r * 128 + qB * 16));
            *(uint4 *)((char *)sBhi + off) = bh[it];
            *(uint4 *)((char *)sBlo + off) = bl[it];
        }
        __syncthreads();
        // ---- prefetch W for next chunk: overlaps the MMA phase below ----
        if (c < 15) {
#pragma unroll
            for (int it = 0; it < 8; ++it)
                wv[it] = *(const float4 *)(Wp + (size_t)it * 16 * H + (c + 1) * 64);
        }
        // ---- 4 ksteps of K=16 ----
#pragma unroll
        for (int ks = 0; ks < 4; ++ks) {
            const int cb0 = ks * 32 + tig * 4;
            const int cb1 = cb0 + 16;
            uint32_t bhf[4][2], blf[4][2];
#pragma unroll
            for (int nt = 0; nt < 4; ++nt) {
                int rn = warpN + nt * 8 + gid;
                bhf[nt][0] = *(const uint32_t *)(cBhi + SWZ(rn * 128 + cb0));
                bhf[nt][1] = *(const uint32_t *)(cBhi + SWZ(rn * 128 + cb1));
                blf[nt][0] = *(const uint32_t *)(cBlo + SWZ(rn * 128 + cb0));
                blf[nt][1] = *(const uint32_t *)(cBlo + SWZ(rn * 128 + cb1));
            }
#pragma unroll
            for (int mt = 0; mt < 2; ++mt) {
                int r0 = warpM + mt * 16 + gid;
                uint32_t ah0 = *(const uint32_t *)(cAhi + SWZ(r0 * 128 + cb0));
                uint32_t ah1 = *(const uint32_t *)(cAhi + SWZ((r0 + 8) * 128 + cb0));
                uint32_t ah2 = *(const uint32_t *)(cAhi + SWZ(r0 * 128 + cb1));
                uint32_t ah3 = *(const uint32_t *)(cAhi + SWZ((r0 + 8) * 128 + cb1));
                uint32_t al0 = *(const uint32_t *)(cAlo + SWZ(r0 * 128 + cb0));
                uint32_t al1 = *(const uint32_t *)(cAlo + SWZ((r0 + 8) * 128 + cb0));
                uint32_t al2 = *(const uint32_t *)(cAlo + SWZ(r0 * 128 + cb1));
                uint32_t al3 = *(const uint32_t *)(cAlo + SWZ((r0 + 8) * 128 + cb1));
#pragma unroll
                for (int nt = 0; nt < 4; ++nt) {
                    MMA16816(acc[mt][nt], ah0, ah1, ah2, ah3, bhf[nt][0], bhf[nt][1]);
                    MMA16816(acc[mt][nt], al0, al1, al2, al3, bhf[nt][0], bhf[nt][1]);
                    MMA16816(acc[mt][nt], ah0, ah1, ah2, ah3, blf[nt][0], blf[nt][1]);
                }
            }
        }
    }

    // ---- epilogue ----
#pragma unroll
    for (int mt = 0; mt < 2; ++mt) {
        int m0 = mBase + warpM + mt * 16 + gid;
        float bv0 = bias[m0], bv1 = bias[m0 + 8];
#pragma unroll
        for (int nt = 0; nt < 4; ++nt) {
            int n0 = warpN + nt * 8 + tig * 2;
            Cout[(size_t)n0 * V + m0]           = acc[mt][nt][0] + bv0;
            Cout[(size_t)(n0 + 1) * V + m0]     = acc[mt][nt][1] + bv0;
            Cout[(size_t)n0 * V + m0 + 8]       = acc[mt][nt][2] + bv1;
            Cout[(size_t)(n0 + 1) * V + m0 + 8] = acc[mt][nt][3] + bv1;
        }
    }
}

// ---------------------------------------------------------------------------
// FMA2 GEMM for the small problems (GRU, concat)
// ---------------------------------------------------------------------------
__global__ void __launch_bounds__(256, 2) gemm128(
    const float *__restrict__ W, const float *__restrict__ X,
    const float *__restrict__ W2, const float *__restrict__ X2,
    const float *__restrict__ bias, float *C, float *C2,
    int M, int K, int kChunk) {
    __shared__ float As[16][128];
    __shared__ float Xd[16][128];
    if (blockIdx.z == 1) { W = W2; X = X2; C = C2; }
    const int tid = threadIdx.x;
    const int mBase = blockIdx.x * 128;
    const int kBase = blockIdx.y * kChunk;
    C += (size_t)blockIdx.y * 64 * M;

    const int ty = tid >> 4;
    const int tx = tid & 15;
    const int lm = tid & 127;
    const int lka = (tid >> 7) << 3;
    const int ln = tid & 63;
    const int lkx = (tid >> 6) << 2;

    const float *Wp = W + (size_t)(mBase + lm) * K + kBase + lka;
    const float *Xp = X + (size_t)ln * K + kBase + lkx;

    float4 wa0 = *(const float4 *)Wp;
    float4 wa1 = *(const float4 *)(Wp + 4);
    float4 xr  = *(const float4 *)Xp;

    u64 acc[4][4];
#pragma unroll
    for (int i = 0; i < 4; i++)
#pragma unroll
        for (int j = 0; j < 4; j++) acc[i][j] = 0ull;

    const int NT = kChunk >> 4;
    for (int kt = 0; kt < NT; ++kt) {
        __syncthreads();
        As[lka + 0][lm] = wa0.x; As[lka + 1][lm] = wa0.y;
        As[lka + 2][lm] = wa0.z; As[lka + 3][lm] = wa0.w;
        As[lka + 4][lm] = wa1.x; As[lka + 5][lm] = wa1.y;
        As[lka + 6][lm] = wa1.z; As[lka + 7][lm] = wa1.w;
        *(u64 *)&Xd[lkx + 0][2 * ln] = pack2(xr.x, xr.x);
        *(u64 *)&Xd[lkx + 1][2 * ln] = pack2(xr.y, xr.y);
        *(u64 *)&Xd[lkx + 2][2 * ln] = pack2(xr.z, xr.z);
        *(u64 *)&Xd[lkx + 3][2 * ln] = pack2(xr.w, xr.w);
        __syncthreads();
        if (kt + 1 < NT) {
            wa0 = *(const float4 *)(Wp + (kt + 1) * 16);
            wa1 = *(const float4 *)(Wp + (kt + 1) * 16 + 4);
            xr  = *(const float4 *)(Xp + (kt + 1) * 16);
        }
#pragma unroll
        for (int k = 0; k < 16; ++k) {
            const ulonglong2 *ar = (const ulonglong2 *)&As[k][ty << 3];
            ulonglong2 a01 = ar[0], a23 = ar[1];
            const ulonglong2 *xp = (const ulonglong2 *)&Xd[k][tx << 3];
            ulonglong2 x01 = xp[0], x23 = xp[1];
            FMA2(acc[0][0], a01.x, x01.x, acc[0][0]);
            FMA2(acc[0][1], a01.x, x01.y, acc[0][1]);
            FMA2(acc[0][2], a01.x, x23.x, acc[0][2]);
            FMA2(acc[0][3], a01.x, x23.y, acc[0][3]);
            FMA2(acc[1][0], a01.y, x01.x, acc[1][0]);
            FMA2(acc[1][1], a01.y, x01.y, acc[1][1]);
            FMA2(acc[1][2], a01.y, x23.x, acc[1][2]);
            FMA2(acc[1][3], a01.y, x23.y, acc[1][3]);
            FMA2(acc[2][0], a23.x, x01.x, acc[2][0]);
            FMA2(acc[2][1], a23.x, x01.y, acc[2][1]);
            FMA2(acc[2][2], a23.x, x23.x, acc[2][2]);
            FMA2(acc[2][3], a23.x, x23.y, acc[2][3]);
            FMA2(acc[3][0], a23.y, x01.x, acc[3][0]);
            FMA2(acc[3][1], a23.y, x01.y, acc[3][1]);
            FMA2(acc[3][2], a23.y, x23.x, acc[3][2]);
            FMA2(acc[3][3], a23.y, x23.y, acc[3][3]);
        }
    }

    float cv[8][4];
#pragma unroll
    for (int mp = 0; mp < 4; mp++)
#pragma unroll
        for (int nj = 0; nj < 4; nj++)
            unpack2(acc[mp][nj], cv[mp * 2][nj], cv[mp * 2 + 1][nj]);

    float bb[8];
    if (bias) {
        float4 b0 = *(const float4 *)(bias + mBase + (ty << 3));
        float4 b1 = *(const float4 *)(bias + mBase + (ty << 3) + 4);
        bb[0] = b0.x; bb[1] = b0.y; bb[2] = b0.z; bb[3] = b0.w;
        bb[4] = b1.x; bb[5] = b1.y; bb[6] = b1.z; bb[7] = b1.w;
    } else {
#pragma unroll
        for (int i = 0; i < 8; i++) bb[i] = 0.f;
    }
#pragma unroll
    for (int nj = 0; nj < 4; nj++) {
        float *cp = C + (size_t)((tx << 2) + nj) * M + mBase + (ty << 3);
        float4 v0 = make_float4(cv[0][nj] + bb[0], cv[1][nj] + bb[1],
                                cv[2][nj] + bb[2], cv[3][nj] + bb[3]);
        float4 v1 = make_float4(cv[4][nj] + bb[4], cv[5][nj] + bb[5],
                                cv[6][nj] + bb[6], cv[7][nj] + bb[7]);
        *(float4 *)cp = v0;
        *(float4 *)(cp + 4) = v1;
    }
}

// ---------------------------------------------------------------------------
__global__ void __launch_bounds__(256) gather_emb(
    const int *__restrict__ seq, const float *__restrict__ emb_table) {
    int idx = blockIdx.x * 256 + threadIdx.x;
    int b = idx >> 8;
    int h4 = (idx & 255) << 2;
    int row = seq[b];
    *(float4 *)(g_emb + b * H + h4) =
        *(const float4 *)(emb_table + (size_t)row * H + h4);
}

// ---------------------------------------------------------------------------
__global__ void __launch_bounds__(256) gru_combine(
    const float *__restrict__ hprev, const float *__restrict__ b_ih,
    const float *__restrict__ b_hh, float *__restrict__ out_hidden) {
    int idx = blockIdx.x * 256 + threadIdx.x;
    int b = idx >> 8;
    int h4 = (idx & 255) << 2;

    float4 gx[3], gh[3];
#pragma unroll
    for (int g = 0; g < 3; g++) {
        gx[g] = *(const float4 *)(b_ih + g * H + h4);
        gh[g] = *(const float4 *)(b_hh + g * H + h4);
#pragma unroll
        for (int s = 0; s < S_GRU; s++) {
            size_t off = ((size_t)s * B + b) * 3 * H + g * H + h4;
            float4 px = *(const float4 *)(g_gxp + off);
            float4 ph = *(const float4 *)(g_ghp + off);
            gx[g].x += px.x; gx[g].y += px.y; gx[g].z += px.z; gx[g].w += px.w;
            gh[g].x += ph.x; gh[g].y += ph.y; gh[g].z += ph.z; gh[g].w += ph.w;
        }
    }
    float4 hp = *(const float4 *)(hprev + b * H + h4);
    float4 ho;
#pragma unroll
    for (int j = 0; j < 4; j++) {
        float xr = (&gx[0].x)[j], xz = (&gx[1].x)[j], xn = (&gx[2].x)[j];
        float hr = (&gh[0].x)[j], hz = (&gh[1].x)[j], hn = (&gh[2].x)[j];
        float r = 1.f / (1.f + expf(-(xr + hr)));
        float z = 1.f / (1.f + expf(-(xz + hz)));
        float n = tanhf(xn + r * hn);
        (&ho.x)[j] = (1.f - z) * n + z * (&hp.x)[j];
    }
    *(float4 *)(g_hnew + b * H + h4) = ho;
    *(float4 *)(out_hidden + b * H + h4) = ho;
    *(float4 *)(g_concat_in + b * 2 * H + h4) = ho;
}

// ---------------------------------------------------------------------------
// Fused attention pass 1: 128 timesteps per CTA (4 blocks of 32).
// ---------------------------------------------------------------------------
__global__ void __launch_bounds__(256, 2) attn_partial(const float *__restrict__ enc) {
    const int b = blockIdx.y;
    const int chunk = blockIdx.x;
    const int t0 = chunk * 128;
    const int tid = threadIdx.x;
    const int warp = tid >> 5, lane = tid & 31;

    __shared__ float sblk[32];
    __shared__ float eblk[32];

    const float *hb = g_hnew + b * H + lane * 4;
    ulonglong2 hv[8];
#pragma unroll
    for (int i = 0; i < 8; i++) hv[i] = *(const ulonglong2 *)(hb + i * 128);

    float M = -1e30f, S = 0.f;
    float4 cacc = make_float4(0.f, 0.f, 0.f, 0.f);
    const float *ebase = enc + ((size_t)t0 * B + b) * H;

    for (int blk = 0; blk < 4; blk++) {
        const int tb = blk * 32;
        float sq[4];
#pragma unroll
        for (int q = 0; q < 4; q++) {
            const int tl = tb + warp * 4 + q;
            const float *e = ebase + (size_t)tl * B * H + lane * 4;
            u64 acc = 0ull;
#pragma unroll
            for (int i = 0; i < 8; i++) {
                ulonglong2 ev = *(const ulonglong2 *)(e + i * 128);
                FMA2(acc, ev.x, hv[i].x, acc);
                FMA2(acc, ev.y, hv[i].y, acc);
            }
            float lo, hi;
            unpack2(acc, lo, hi);
            float s = lo + hi;
#pragma unroll
            for (int o = 16; o; o >>= 1) s += __shfl_xor_sync(0xffffffffu, s, o);
            sq[q] = s;
            if (!lane) g_scores[b * T + t0 + tl] = s;
        }
        if (!lane) {
            sblk[warp * 4 + 0] = sq[0]; sblk[warp * 4 + 1] = sq[1];
            sblk[warp * 4 + 2] = sq[2]; sblk[warp * 4 + 3] = sq[3];
        }
        __syncthreads();
        float m_blk = sblk[0];
#pragma unroll
        for (int i = 1; i < 32; i++) m_blk = fmaxf(m_blk, sblk[i]);
        float Mn = fmaxf(M, m_blk);
        float r = expf(M - Mn);
        if (tid < 32) eblk[tid] = expf(sblk[tid] - Mn);
        __syncthreads();
        float es = 0.f;
#pragma unroll
        for (int i = 0; i < 32; i++) es += eblk[i];
        S = S * r + es;
        M = Mn;
        cacc.x *= r; cacc.y *= r; cacc.z *= r; cacc.w *= r;
        const float *e2 = ebase + (size_t)tb * B * H + tid * 4;
#pragma unroll 8
        for (int t = 0; t < 32; t++) {
            float w = eblk[t];
            float4 ev = *(const float4 *)(e2 + (size_t)t * B * H);
            cacc.x += w * ev.x; cacc.y += w * ev.y;
            cacc.z += w * ev.z; cacc.w += w * ev.w;
        }
        __syncthreads();
    }

    *(float4 *)(g_ctxpart + ((size_t)b * NCHUNK + chunk) * H + tid * 4) = cacc;
    if (tid == 0) {
        g_pm[b * NCHUNK + chunk] = M;
        g_ps[b * NCHUNK + chunk] = S;
    }
}

// ---------------------------------------------------------------------------
__global__ void __launch_bounds__(256) attn_combine(float *__restrict__ attn_out) {
    const int b = blockIdx.x;
    const int tid = threadIdx.x;

    float m[NCHUNK], s[NCHUNK];
#pragma unroll
    for (int j = 0; j < NCHUNK; j++) {
        m[j] = g_pm[b * NCHUNK + j];
        s[j] = g_ps[b * NCHUNK + j];
    }
    float gm = m[0];
#pragma unroll
    for (int j = 1; j < NCHUNK; j++) gm = fmaxf(gm, m[j]);
    float gsum = 0.f;
    float f[NCHUNK];
#pragma unroll
    for (int j = 0; j < NCHUNK; j++) {
        f[j] = expf(m[j] - gm);
        gsum += f[j] * s[j];
    }
    float inv = 1.f / gsum;

    int h4 = tid * 4;
    float4 c = make_float4(0.f, 0.f, 0.f, 0.f);
#pragma unroll
    for (int j = 0; j < NCHUNK; j++) {
        float4 p = *(const float4 *)(g_ctxpart + ((size_t)b * NCHUNK + j) * H + h4);
        float fj = f[j] * inv;
        c.x += fj * p.x; c.y += fj * p.y; c.z += fj * p.z; c.w += fj * p.w;
    }
    *(float4 *)(g_concat_in + b * 2 * H + H + h4) = c;

    float4 sc = *(const float4 *)(g_scores + b * T + tid * 4);
    float4 a = make_float4(expf(sc.x - gm) * inv, expf(sc.y - gm) * inv,
                           expf(sc.z - gm) * inv, expf(sc.w - gm) * inv);
    *(float4 *)(attn_out + b * T + tid * 4) = a;
}

// ---------------------------------------------------------------------------
// Concat reduce: split-K sum + bias + tanh, emit bf16 hi/lo directly (fused
// xconvert: removes one kernel and a fp32 round-trip).
// ---------------------------------------------------------------------------
__global__ void __launch_bounds__(256) concat_reduce(const float *__restrict__ cb) {
    int idx = blockIdx.x * 256 + threadIdx.x;  // B*H/4
    int b = idx >> 8;
    int h4 = (idx & 255) << 2;
    float4 s = *(const float4 *)(cb + h4);
#pragma unroll
    for (int j = 0; j < S_CAT; j++) {
        float4 p = *(const float4 *)(g_cp + ((size_t)j * B + b) * H + h4);
        s.x += p.x; s.y += p.y; s.z += p.z; s.w += p.w;
    }
    s.x = tanhf(s.x); s.y = tanhf(s.y); s.z = tanhf(s.z); s.w = tanhf(s.w);

    __nv_bfloat162 h01 = __float22bfloat162_rn(make_float2(s.x, s.y));
    __nv_bfloat162 h23 = __float22bfloat162_rn(make_float2(s.z, s.w));
    float2 f01 = __bfloat1622float2(h01);
    float2 f23 = __bfloat1622float2(h23);
    __nv_bfloat162 l01 = __float22bfloat162_rn(make_float2(s.x - f01.x, s.y - f01.y));
    __nv_bfloat162 l23 = __float22bfloat162_rn(make_float2(s.z - f23.x, s.w - f23.y));
    size_t o = (size_t)b * H + h4;
    *(uint2 *)(g_xhi + o) = make_uint2(*(uint32_t *)&h01, *(uint32_t *)&h23);
    *(uint2 *)(g_xlo + o) = make_uint2(*(uint32_t *)&l01, *(uint32_t *)&l23);
}

// ---------------------------------------------------------------------------
extern "C" void kernel_launch(void *const *d_in, const int *in_sizes, int n_in,
                              void *d_out, int out_size) {
    const int *seq     = (const int *)d_in[0];
    const float *hprev = (const float *)d_in[1];
    const float *enc   = (const float *)d_in[2];
    const float *emb   = (const float *)d_in[3];
    const float *w_ih  = (const float *)d_in[4];
    const float *w_hh  = (const float *)d_in[5];
    const float *b_ih  = (const float *)d_in[6];
    const float *b_hh  = (const float *)d_in[7];
    const float *cW    = (const float *)d_in[8];
    const float *cb    = (const float *)d_in[9];
    const float *oW    = (const float *)d_in[10];
    const float *ob    = (const float *)d_in[11];
    float *out = (float *)d_out;

    float *p_emb, *p_gxp, *p_ghp, *p_cin, *p_cp;
    cudaGetSymbolAddress((void **)&p_emb,  g_emb);
    cudaGetSymbolAddress((void **)&p_gxp,  g_gxp);
    cudaGetSymbolAddress((void **)&p_ghp,  g_ghp);
    cudaGetSymbolAddress((void **)&p_cin,  g_concat_in);
    cudaGetSymbolAddress((void **)&p_cp,   g_cp);

    float *out_hidden = out + (size_t)B * V;
    float *out_attn   = out + (size_t)B * V + (size_t)B * H;

    // 1) embedding gather
    gather_emb<<<64, 256>>>(seq, emb);
    // 2) both GRU GEMMs fused, split-K=4
    gemm128<<<dim3(3 * H / 128, S_GRU, 2), 256>>>(
        w_ih, p_emb, w_hh, hprev, nullptr, p_gxp, p_ghp, 3 * H, H, H / S_GRU);
    // 3) gate combine
    gru_combine<<<64, 256>>>(hprev, b_ih, b_hh, out_hidden);
    // 4) fused attention (8 chunks x 64 b = 512 CTAs)
    attn_partial<<<dim3(NCHUNK, B), 256>>>(enc);
    attn_combine<<<B, 256>>>(out_attn);
    // 5) concat GEMM split-K=16; reduce fuses bias+tanh+bf16 conversion
    gemm128<<<dim3(H / 128, S_CAT, 1), 256>>>(
        cW, p_cin, cW, p_cin, nullptr, p_cp, p_cp, H, 2 * H, 2 * H / S_CAT);
    concat_reduce<<<64, 256>>>(cb);
    // 6) output GEMM on mma.sync bf16 (split precision, pipelined)
    out_gemm_mma<<<V / 128, 256>>>(oW, ob, out);
}

// round 15
// speedup vs baseline: 1.3951x; 1.3951x over previous
#include <cuda_runtime.h>
#include <cuda_bf16.h>
#include <math.h>
#include <stdint.h>

#define B 64
#define H 1024
#define T 1024
#define V 32000

#define S_GRU 4   // split-K for GRU gemms
#define S_CAT 16  // split-K for concat gemm
#define NCHUNK 4  // attention t-chunks (256 t each)  [reverted: measured best]

// ---------------- scratch (alloc-free: __device__ globals) ----------------
__device__ float g_emb[B * H];
__device__ float g_gxp[S_GRU * B * 3 * H];
__device__ float g_ghp[S_GRU * B * 3 * H];
__device__ float g_hnew[B * H];
__device__ float g_scores[B * T];
__device__ float g_pm[B * NCHUNK];
__device__ float g_ps[B * NCHUNK];
__device__ float g_ctxpart[B * NCHUNK * H];
__device__ float g_concat_in[B * 2 * H];
__device__ float g_cp[S_CAT * B * H];
__device__ __nv_bfloat16 g_xhi[B * H];
__device__ __nv_bfloat16 g_xlo[B * H];

typedef unsigned long long u64;

__device__ __forceinline__ u64 pack2(float lo, float hi) {
    u64 r;
    asm("mov.b64 %0, {%1, %2};" : "=l"(r) : "f"(lo), "f"(hi));
    return r;
}
__device__ __forceinline__ void unpack2(u64 v, float &lo, float &hi) {
    asm("mov.b64 {%0, %1}, %2;" : "=f"(lo), "=f"(hi) : "l"(v));
}
#define FMA2(d, a, b, c) \
    asm("fma.rn.f32x2 %0, %1, %2, %3;" : "=l"(d) : "l"(a), "l"(b), "l"(c))

#define SWZ(o) ((o) ^ ((((uint32_t)(o)) >> 3) & 0x70))

#define MMA16816(d, a0, a1, a2, a3, b0, b1)                             \
    asm volatile(                                                       \
        "mma.sync.aligned.m16n8k16.row.col.f32.bf16.bf16.f32 "          \
        "{%0,%1,%2,%3}, {%4,%5,%6,%7}, {%8,%9}, {%0,%1,%2,%3};"         \
        : "+f"((d)[0]), "+f"((d)[1]), "+f"((d)[2]), "+f"((d)[3])        \
        : "r"(a0), "r"(a1), "r"(a2), "r"(a3), "r"(b0), "r"(b1))

#define LDSM4(r0, r1, r2, r3, addr)                                     \
    asm volatile(                                                       \
        "ldmatrix.sync.aligned.m8n8.x4.shared.b16 {%0,%1,%2,%3}, [%4];" \
        : "=r"(r0), "=r"(r1), "=r"(r2), "=r"(r3) : "r"(addr))

__device__ __forceinline__ uint32_t smem_u32(const void *p) {
    uint32_t a;
    asm("{ .reg .u64 t; cvta.to.shared.u64 t, %1; cvt.u32.u64 %0, t; }"
        : "=r"(a) : "l"(p));
    return a;
}

// ---------------------------------------------------------------------------
// Output GEMM via mma.sync bf16 (split precision).
// Round-10 structure (global loads at loop top; wv dead before MMA phase),
// but fragment loads via ldmatrix.x4: 6 LDSM/kstep vs 32 LDS.32 — removes
// the smem-issue bottleneck. SW128 property used: the kstep byte offset
// (bits 4-6) commutes with the swizzle, so addr = base ^ kb.
// CTA: 128m x 64n, K chunks of 64; 8 warps of 32m x 32n.
// D = Whi.Xhi + Wlo.Xhi + Whi.Xlo (fp32 accumulate).
// ---------------------------------------------------------------------------
__global__ void __launch_bounds__(256) out_gemm_mma(
    const float *__restrict__ W, const float *__restrict__ bias,
    float *__restrict__ Cout) {
    __shared__ __align__(128) __nv_bfloat16 sAhi[128 * 64];
    __shared__ __align__(128) __nv_bfloat16 sAlo[128 * 64];
    __shared__ __align__(128) __nv_bfloat16 sBhi[64 * 64];
    __shared__ __align__(128) __nv_bfloat16 sBlo[64 * 64];

    const int tid = threadIdx.x;
    const int lane = tid & 31;
    const int warp = tid >> 5;
    const int mBase = blockIdx.x * 128;

    const int warpM = (warp & 3) * 32;
    const int warpN = (warp >> 2) * 32;
    const int gid = lane >> 2;   // 0..7
    const int tig = lane & 3;    // 0..3

    const int rowA = tid >> 4;   // 0..15 (+16 per iter, 8 iters)
    const int kq = tid & 15;     // float4 within 64-k chunk
    const int rowB = tid >> 3;   // 0..31 (+32 per iter, 2 iters)
    const int qB = tid & 7;      // uint4 within 128B row

    // ldmatrix per-lane address bases (swizzled row part; kstep XORed in)
    const uint32_t uAhi = smem_u32(sAhi), uAlo = smem_u32(sAlo);
    const uint32_t uBhi = smem_u32(sBhi), uBlo = smem_u32(sBlo);
    const uint32_t kbA = (uint32_t)((lane >> 4) << 4);  // 0 / 16
    const int q2 = lane >> 3, idx8 = lane & 7;
    const uint32_t kbB = (uint32_t)((q2 & 1) << 4);
    uint32_t abase[2], bbase[2];
#pragma unroll
    for (int mt = 0; mt < 2; ++mt)
        abase[mt] = SWZ((uint32_t)((warpM + mt * 16 + (lane & 15)) * 128));
#pragma unroll
    for (int np = 0; np < 2; ++np)
        bbase[np] =
            SWZ((uint32_t)((warpN + (np * 2 + (q2 >> 1)) * 8 + idx8) * 128));

    float acc[2][4][4];
#pragma unroll
    for (int i = 0; i < 2; i++)
#pragma unroll
        for (int j = 0; j < 4; j++)
#pragma unroll
            for (int qq = 0; qq < 4; qq++) acc[i][j][qq] = 0.f;

    for (int c = 0; c < 16; ++c) {
        const int k0 = c * 64;
        // ---- global loads first (in flight across the first sync) ----
        float4 wv[8];
#pragma unroll
        for (int it = 0; it < 8; ++it) {
            int r = rowA + it * 16;
            wv[it] = *(const float4 *)(W + (size_t)(mBase + r) * H + k0 + kq * 4);
        }
        uint4 bh[2], bl[2];
#pragma unroll
        for (int it = 0; it < 2; ++it) {
            int r = rowB + it * 32;
            bh[it] = *(const uint4 *)(g_xhi + (size_t)r * H + k0 + qB * 8);
            bl[it] = *(const uint4 *)(g_xlo + (size_t)r * H + k0 + qB * 8);
        }
        __syncthreads();  // previous chunk fully consumed
        // ---- convert W -> bf16 hi/lo, store swizzled ----
#pragma unroll
        for (int it = 0; it < 8; ++it) {
            int r = rowA + it * 16;
            uint32_t off = SWZ((uint32_t)(r * 128 + kq * 8));
            __nv_bfloat162 h01 = __float22bfloat162_rn(make_float2(wv[it].x, wv[it].y));
            __nv_bfloat162 h23 = __float22bfloat162_rn(make_float2(wv[it].z, wv[it].w));
            float2 f01 = __bfloat1622float2(h01);
            float2 f23 = __bfloat1622float2(h23);
            __nv_bfloat162 l01 = __float22bfloat162_rn(
                make_float2(wv[it].x - f01.x, wv[it].y - f01.y));
            __nv_bfloat162 l23 = __float22bfloat162_rn(
                make_float2(wv[it].z - f23.x, wv[it].w - f23.y));
            *(uint2 *)((char *)sAhi + off) =
                make_uint2(*(uint32_t *)&h01, *(uint32_t *)&h23);
            *(uint2 *)((char *)sAlo + off) =
                make_uint2(*(uint32_t *)&l01, *(uint32_t *)&l23);
        }
#pragma unroll
        for (int it = 0; it < 2; ++it) {
            int r = rowB + it * 32;
            uint32_t off = SWZ((uint32_t)(r * 128 + qB * 16));
            *(uint4 *)((char *)sBhi + off) = bh[it];
            *(uint4 *)((char *)sBlo + off) = bl[it];
        }
        __syncthreads();
        // ---- 4 ksteps of K=16, fragments via ldmatrix ----
#pragma unroll
        for (int ks = 0; ks < 4; ++ks) {
            const uint32_t kb = (uint32_t)(ks * 32);
            uint32_t bhf[8], blf[8];  // [nt*2 + kreg]
            LDSM4(bhf[0], bhf[1], bhf[2], bhf[3], uBhi + (bbase[0] ^ (kb + kbB)));
            LDSM4(bhf[4], bhf[5], bhf[6], bhf[7], uBhi + (bbase[1] ^ (kb + kbB)));
            LDSM4(blf[0], blf[1], blf[2], blf[3], uBlo + (bbase[0] ^ (kb + kbB)));
            LDSM4(blf[4], blf[5], blf[6], blf[7], uBlo + (bbase[1] ^ (kb + kbB)));
#pragma unroll
            for (int mt = 0; mt < 2; ++mt) {
                uint32_t ah[4], al[4];
                LDSM4(ah[0], ah[1], ah[2], ah[3], uAhi + (abase[mt] ^ (kb + kbA)));
                LDSM4(al[0], al[1], al[2], al[3], uAlo + (abase[mt] ^ (kb + kbA)));
#pragma unroll
                for (int nt = 0; nt < 4; ++nt) {
                    MMA16816(acc[mt][nt], ah[0], ah[1], ah[2], ah[3],
                             bhf[nt * 2], bhf[nt * 2 + 1]);
                    MMA16816(acc[mt][nt], al[0], al[1], al[2], al[3],
                             bhf[nt * 2], bhf[nt * 2 + 1]);
                    MMA16816(acc[mt][nt], ah[0], ah[1], ah[2], ah[3],
                             blf[nt * 2], blf[nt * 2 + 1]);
                }
            }
        }
    }

    // ---- epilogue ----
#pragma unroll
    for (int mt = 0; mt < 2; ++mt) {
        int m0 = mBase + warpM + mt * 16 + gid;
        float bv0 = bias[m0], bv1 = bias[m0 + 8];
#pragma unroll
        for (int nt = 0; nt < 4; ++nt) {
            int n0 = warpN + nt * 8 + tig * 2;
            Cout[(size_t)n0 * V + m0]           = acc[mt][nt][0] + bv0;
            Cout[(size_t)(n0 + 1) * V + m0]     = acc[mt][nt][1] + bv0;
            Cout[(size_t)n0 * V + m0 + 8]       = acc[mt][nt][2] + bv1;
            Cout[(size_t)(n0 + 1) * V + m0 + 8] = acc[mt][nt][3] + bv1;
        }
    }
}

// ---------------------------------------------------------------------------
// FMA2 GEMM for the small problems (GRU, concat)
// ---------------------------------------------------------------------------
__global__ void __launch_bounds__(256, 2) gemm128(
    const float *__restrict__ W, const float *__restrict__ X,
    const float *__restrict__ W2, const float *__restrict__ X2,
    const float *__restrict__ bias, float *C, float *C2,
    int M, int K, int kChunk) {
    __shared__ float As[16][128];
    __shared__ float Xd[16][128];
    if (blockIdx.z == 1) { W = W2; X = X2; C = C2; }
    const int tid = threadIdx.x;
    const int mBase = blockIdx.x * 128;
    const int kBase = blockIdx.y * kChunk;
    C += (size_t)blockIdx.y * 64 * M;

    const int ty = tid >> 4;
    const int tx = tid & 15;
    const int lm = tid & 127;
    const int lka = (tid >> 7) << 3;
    const int ln = tid & 63;
    const int lkx = (tid >> 6) << 2;

    const float *Wp = W + (size_t)(mBase + lm) * K + kBase + lka;
    const float *Xp = X + (size_t)ln * K + kBase + lkx;

    float4 wa0 = *(const float4 *)Wp;
    float4 wa1 = *(const float4 *)(Wp + 4);
    float4 xr  = *(const float4 *)Xp;

    u64 acc[4][4];
#pragma unroll
    for (int i = 0; i < 4; i++)
#pragma unroll
        for (int j = 0; j < 4; j++) acc[i][j] = 0ull;

    const int NT = kChunk >> 4;
    for (int kt = 0; kt < NT; ++kt) {
        __syncthreads();
        As[lka + 0][lm] = wa0.x; As[lka + 1][lm] = wa0.y;
        As[lka + 2][lm] = wa0.z; As[lka + 3][lm] = wa0.w;
        As[lka + 4][lm] = wa1.x; As[lka + 5][lm] = wa1.y;
        As[lka + 6][lm] = wa1.z; As[lka + 7][lm] = wa1.w;
        *(u64 *)&Xd[lkx + 0][2 * ln] = pack2(xr.x, xr.x);
        *(u64 *)&Xd[lkx + 1][2 * ln] = pack2(xr.y, xr.y);
        *(u64 *)&Xd[lkx + 2][2 * ln] = pack2(xr.z, xr.z);
        *(u64 *)&Xd[lkx + 3][2 * ln] = pack2(xr.w, xr.w);
        __syncthreads();
        if (kt + 1 < NT) {
            wa0 = *(const float4 *)(Wp + (kt + 1) * 16);
            wa1 = *(const float4 *)(Wp + (kt + 1) * 16 + 4);
            xr  = *(const float4 *)(Xp + (kt + 1) * 16);
        }
#pragma unroll
        for (int k = 0; k < 16; ++k) {
            const ulonglong2 *ar = (const ulonglong2 *)&As[k][ty << 3];
            ulonglong2 a01 = ar[0], a23 = ar[1];
            const ulonglong2 *xp = (const ulonglong2 *)&Xd[k][tx << 3];
            ulonglong2 x01 = xp[0], x23 = xp[1];
            FMA2(acc[0][0], a01.x, x01.x, acc[0][0]);
            FMA2(acc[0][1], a01.x, x01.y, acc[0][1]);
            FMA2(acc[0][2], a01.x, x23.x, acc[0][2]);
            FMA2(acc[0][3], a01.x, x23.y, acc[0][3]);
            FMA2(acc[1][0], a01.y, x01.x, acc[1][0]);
            FMA2(acc[1][1], a01.y, x01.y, acc[1][1]);
            FMA2(acc[1][2], a01.y, x23.x, acc[1][2]);
            FMA2(acc[1][3], a01.y, x23.y, acc[1][3]);
            FMA2(acc[2][0], a23.x, x01.x, acc[2][0]);
            FMA2(acc[2][1], a23.x, x01.y, acc[2][1]);
            FMA2(acc[2][2], a23.x, x23.x, acc[2][2]);
            FMA2(acc[2][3], a23.x, x23.y, acc[2][3]);
            FMA2(acc[3][0], a23.y, x01.x, acc[3][0]);
            FMA2(acc[3][1], a23.y, x01.y, acc[3][1]);
            FMA2(acc[3][2], a23.y, x23.x, acc[3][2]);
            FMA2(acc[3][3], a23.y, x23.y, acc[3][3]);
        }
    }

    float cv[8][4];
#pragma unroll
    for (int mp = 0; mp < 4; mp++)
#pragma unroll
        for (int nj = 0; nj < 4; nj++)
            unpack2(acc[mp][nj], cv[mp * 2][nj], cv[mp * 2 + 1][nj]);

    float bb[8];
    if (bias) {
        float4 b0 = *(const float4 *)(bias + mBase + (ty << 3));
        float4 b1 = *(const float4 *)(bias + mBase + (ty << 3) + 4);
        bb[0] = b0.x; bb[1] = b0.y; bb[2] = b0.z; bb[3] = b0.w;
        bb[4] = b1.x; bb[5] = b1.y; bb[6] = b1.z; bb[7] = b1.w;
    } else {
#pragma unroll
        for (int i = 0; i < 8; i++) bb[i] = 0.f;
    }
#pragma unroll
    for (int nj = 0; nj < 4; nj++) {
        float *cp = C + (size_t)((tx << 2) + nj) * M + mBase + (ty << 3);
        float4 v0 = make_float4(cv[0][nj] + bb[0], cv[1][nj] + bb[1],
                                cv[2][nj] + bb[2], cv[3][nj] + bb[3]);
        float4 v1 = make_float4(cv[4][nj] + bb[4], cv[5][nj] + bb[5],
                                cv[6][nj] + bb[6], cv[7][nj] + bb[7]);
        *(float4 *)cp = v0;
        *(float4 *)(cp + 4) = v1;
    }
}

// ---------------------------------------------------------------------------
__global__ void __launch_bounds__(256) gather_emb(
    const int *__restrict__ seq, const float *__restrict__ emb_table) {
    int idx = blockIdx.x * 256 + threadIdx.x;
    int b = idx >> 8;
    int h4 = (idx & 255) << 2;
    int row = seq[b];
    *(float4 *)(g_emb + b * H + h4) =
        *(const float4 *)(emb_table + (size_t)row * H + h4);
}

// ---------------------------------------------------------------------------
__global__ void __launch_bounds__(256) gru_combine(
    const float *__restrict__ hprev, const float *__restrict__ b_ih,
    const float *__restrict__ b_hh, float *__restrict__ out_hidden) {
    int idx = blockIdx.x * 256 + threadIdx.x;
    int b = idx >> 8;
    int h4 = (idx & 255) << 2;

    float4 gx[3], gh[3];
#pragma unroll
    for (int g = 0; g < 3; g++) {
        gx[g] = *(const float4 *)(b_ih + g * H + h4);
        gh[g] = *(const float4 *)(b_hh + g * H + h4);
#pragma unroll
        for (int s = 0; s < S_GRU; s++) {
            size_t off = ((size_t)s * B + b) * 3 * H + g * H + h4;
            float4 px = *(const float4 *)(g_gxp + off);
            float4 ph = *(const float4 *)(g_ghp + off);
            gx[g].x += px.x; gx[g].y += px.y; gx[g].z += px.z; gx[g].w += px.w;
            gh[g].x += ph.x; gh[g].y += ph.y; gh[g].z += ph.z; gh[g].w += ph.w;
        }
    }
    float4 hp = *(const float4 *)(hprev + b * H + h4);
    float4 ho;
#pragma unroll
    for (int j = 0; j < 4; j++) {
        float xr = (&gx[0].x)[j], xz = (&gx[1].x)[j], xn = (&gx[2].x)[j];
        float hr = (&gh[0].x)[j], hz = (&gh[1].x)[j], hn = (&gh[2].x)[j];
        float r = 1.f / (1.f + expf(-(xr + hr)));
        float z = 1.f / (1.f + expf(-(xz + hz)));
        float n = tanhf(xn + r * hn);
        (&ho.x)[j] = (1.f - z) * n + z * (&hp.x)[j];
    }
    *(float4 *)(g_hnew + b * H + h4) = ho;
    *(float4 *)(out_hidden + b * H + h4) = ho;
    *(float4 *)(g_concat_in + b * 2 * H + h4) = ho;
}

// ---------------------------------------------------------------------------
// Fused attention pass 1: 256 timesteps per CTA (8 blocks of 32). [round-10]
// ---------------------------------------------------------------------------
__global__ void __launch_bounds__(256, 2) attn_partial(const float *__restrict__ enc) {
    const int b = blockIdx.y;
    const int chunk = blockIdx.x;
    const int t0 = chunk * 256;
    const int tid = threadIdx.x;
    const int warp = tid >> 5, lane = tid & 31;

    __shared__ float sblk[32];
    __shared__ float eblk[32];

    const float *hb = g_hnew + b * H + lane * 4;
    ulonglong2 hv[8];
#pragma unroll
    for (int i = 0; i < 8; i++) hv[i] = *(const ulonglong2 *)(hb + i * 128);

    float M = -1e30f, S = 0.f;
    float4 cacc = make_float4(0.f, 0.f, 0.f, 0.f);
    const float *ebase = enc + ((size_t)t0 * B + b) * H;

    for (int blk = 0; blk < 8; blk++) {
        const int tb = blk * 32;
        float sq[4];
#pragma unroll
        for (int q = 0; q < 4; q++) {
            const int tl = tb + warp * 4 + q;
            const float *e = ebase + (size_t)tl * B * H + lane * 4;
            u64 acc = 0ull;
#pragma unroll
            for (int i = 0; i < 8; i++) {
                ulonglong2 ev = *(const ulonglong2 *)(e + i * 128);
                FMA2(acc, ev.x, hv[i].x, acc);
                FMA2(acc, ev.y, hv[i].y, acc);
            }
            float lo, hi;
            unpack2(acc, lo, hi);
            float s = lo + hi;
#pragma unroll
            for (int o = 16; o; o >>= 1) s += __shfl_xor_sync(0xffffffffu, s, o);
            sq[q] = s;
            if (!lane) g_scores[b * T + t0 + tl] = s;
        }
        if (!lane) {
            sblk[warp * 4 + 0] = sq[0]; sblk[warp * 4 + 1] = sq[1];
            sblk[warp * 4 + 2] = sq[2]; sblk[warp * 4 + 3] = sq[3];
        }
        __syncthreads();
        float m_blk = sblk[0];
#pragma unroll
        for (int i = 1; i < 32; i++) m_blk = fmaxf(m_blk, sblk[i]);
        float Mn = fmaxf(M, m_blk);
        float r = expf(M - Mn);
        if (tid < 32) eblk[tid] = expf(sblk[tid] - Mn);
        __syncthreads();
        float es = 0.f;
#pragma unroll
        for (int i = 0; i < 32; i++) es += eblk[i];
        S = S * r + es;
        M = Mn;
        cacc.x *= r; cacc.y *= r; cacc.z *= r; cacc.w *= r;
        const float *e2 = ebase + (size_t)tb * B * H + tid * 4;
#pragma unroll 8
        for (int t = 0; t < 32; t++) {
            float w = eblk[t];
            float4 ev = *(const float4 *)(e2 + (size_t)t * B * H);
            cacc.x += w * ev.x; cacc.y += w * ev.y;
            cacc.z += w * ev.z; cacc.w += w * ev.w;
        }
        __syncthreads();
    }

    *(float4 *)(g_ctxpart + ((size_t)b * NCHUNK + chunk) * H + tid * 4) = cacc;
    if (tid == 0) {
        g_pm[b * NCHUNK + chunk] = M;
        g_ps[b * NCHUNK + chunk] = S;
    }
}

// ---------------------------------------------------------------------------
__global__ void __launch_bounds__(256) attn_combine(float *__restrict__ attn_out) {
    const int b = blockIdx.x;
    const int tid = threadIdx.x;

    float m[NCHUNK], s[NCHUNK];
#pragma unroll
    for (int j = 0; j < NCHUNK; j++) {
        m[j] = g_pm[b * NCHUNK + j];
        s[j] = g_ps[b * NCHUNK + j];
    }
    float gm = m[0];
#pragma unroll
    for (int j = 1; j < NCHUNK; j++) gm = fmaxf(gm, m[j]);
    float gsum = 0.f;
    float f[NCHUNK];
#pragma unroll
    for (int j = 0; j < NCHUNK; j++) {
        f[j] = expf(m[j] - gm);
        gsum += f[j] * s[j];
    }
    float inv = 1.f / gsum;

    int h4 = tid * 4;
    float4 c = make_float4(0.f, 0.f, 0.f, 0.f);
#pragma unroll
    for (int j = 0; j < NCHUNK; j++) {
        float4 p = *(const float4 *)(g_ctxpart + ((size_t)b * NCHUNK + j) * H + h4);
        float fj = f[j] * inv;
        c.x += fj * p.x; c.y += fj * p.y; c.z += fj * p.z; c.w += fj * p.w;
    }
    *(float4 *)(g_concat_in + b * 2 * H + H + h4) = c;

    float4 sc = *(const float4 *)(g_scores + b * T + tid * 4);
    float4 a = make_float4(expf(sc.x - gm) * inv, expf(sc.y - gm) * inv,
                           expf(sc.z - gm) * inv, expf(sc.w - gm) * inv);
    *(float4 *)(attn_out + b * T + tid * 4) = a;
}

// ---------------------------------------------------------------------------
// Concat reduce: split-K sum + bias + tanh, emit bf16 hi/lo directly.
// ---------------------------------------------------------------------------
__global__ void __launch_bounds__(256) concat_reduce(const float *__restrict__ cb) {
    int idx = blockIdx.x * 256 + threadIdx.x;  // B*H/4
    int b = idx >> 8;
    int h4 = (idx & 255) << 2;
    float4 s = *(const float4 *)(cb + h4);
#pragma unroll
    for (int j = 0; j < S_CAT; j++) {
        float4 p = *(const float4 *)(g_cp + ((size_t)j * B + b) * H + h4);
        s.x += p.x; s.y += p.y; s.z += p.z; s.w += p.w;
    }
    s.x = tanhf(s.x); s.y = tanhf(s.y); s.z = tanhf(s.z); s.w = tanhf(s.w);

    __nv_bfloat162 h01 = __float22bfloat162_rn(make_float2(s.x, s.y));
    __nv_bfloat162 h23 = __float22bfloat162_rn(make_float2(s.z, s.w));
    float2 f01 = __bfloat1622float2(h01);
    float2 f23 = __bfloat1622float2(h23);
    __nv_bfloat162 l01 = __float22bfloat162_rn(make_float2(s.x - f01.x, s.y - f01.y));
    __nv_bfloat162 l23 = __float22bfloat162_rn(make_float2(s.z - f23.x, s.w - f23.y));
    size_t o = (size_t)b * H + h4;
    *(uint2 *)(g_xhi + o) = make_uint2(*(uint32_t *)&h01, *(uint32_t *)&h23);
    *(uint2 *)(g_xlo + o) = make_uint2(*(uint32_t *)&l01, *(uint32_t *)&l23);
}

// ---------------------------------------------------------------------------
extern "C" void kernel_launch(void *const *d_in, const int *in_sizes, int n_in,
                              void *d_out, int out_size) {
    const int *seq     = (const int *)d_in[0];
    const float *hprev = (const float *)d_in[1];
    const float *enc   = (const float *)d_in[2];
    const float *emb   = (const float *)d_in[3];
    const float *w_ih  = (const float *)d_in[4];
    const float *w_hh  = (const float *)d_in[5];
    const float *b_ih  = (const float *)d_in[6];
    const float *b_hh  = (const float *)d_in[7];
    const float *cW    = (const float *)d_in[8];
    const float *cb    = (const float *)d_in[9];
    const float *oW    = (const float *)d_in[10];
    const float *ob    = (const float *)d_in[11];
    float *out = (float *)d_out;

    float *p_emb, *p_gxp, *p_ghp, *p_cin, *p_cp;
    cudaGetSymbolAddress((void **)&p_emb,  g_emb);
    cudaGetSymbolAddress((void **)&p_gxp,  g_gxp);
    cudaGetSymbolAddress((void **)&p_ghp,  g_ghp);
    cudaGetSymbolAddress((void **)&p_cin,  g_concat_in);
    cudaGetSymbolAddress((void **)&p_cp,   g_cp);

    float *out_hidden = out + (size_t)B * V;
    float *out_attn   = out + (size_t)B * V + (size_t)B * H;

    // 1) embedding gather
    gather_emb<<<64, 256>>>(seq, emb);
    // 2) both GRU GEMMs fused, split-K=4
    gemm128<<<dim3(3 * H / 128, S_GRU, 2), 256>>>(
        w_ih, p_emb, w_hh, hprev, nullptr, p_gxp, p_ghp, 3 * H, H, H / S_GRU);
    // 3) gate combine
    gru_combine<<<64, 256>>>(hprev, b_ih, b_hh, out_hidden);
    // 4) fused attention (4 chunks x 64 b = 256 CTAs)
    attn_partial<<<dim3(NCHUNK, B), 256>>>(enc);
    attn_combine<<<B, 256>>>(out_attn);
    // 5) concat GEMM split-K=16; reduce fuses bias+tanh+bf16 conversion
    gemm128<<<dim3(H / 128, S_CAT, 1), 256>>>(
        cW, p_cin, cW, p_cin, nullptr, p_cp, p_cp, H, 2 * H, 2 * H / S_CAT);
    concat_reduce<<<64, 256>>>(cb);
    // 6) output GEMM on mma.sync bf16 (split precision, ldmatrix fragments)
    out_gemm_mma<<<V / 128, 256>>>(oW, ob, out);
}

// round 17
// speedup vs baseline: 1.5282x; 1.0954x over previous
#include <cuda_runtime.h>
#include <cuda_bf16.h>
#include <math.h>
#include <stdint.h>

#define B 64
#define H 1024
#define T 1024
#define V 32000

#define S_GRU 4   // split-K for GRU gemms
#define S_CAT 16  // split-K for concat gemm
#define NCHUNK 4  // attention t-chunks (256 t each)

// ---------------- scratch (alloc-free: __device__ globals) ----------------
__device__ float g_emb[B * H];
__device__ float g_gxp[S_GRU * B * 3 * H];
__device__ float g_ghp[S_GRU * B * 3 * H];
__device__ float g_hnew[B * H];
__device__ float g_scores[B * T];
__device__ float g_pm[B * NCHUNK];
__device__ float g_ps[B * NCHUNK];
__device__ float g_ctxpart[B * NCHUNK * H];
__device__ float g_concat_in[B * 2 * H];
__device__ float g_cp[S_CAT * B * H];
__device__ __nv_bfloat16 g_xhi[B * H];
__device__ __nv_bfloat16 g_xlo[B * H];

typedef unsigned long long u64;

__device__ __forceinline__ u64 pack2(float lo, float hi) {
    u64 r;
    asm("mov.b64 %0, {%1, %2};" : "=l"(r) : "f"(lo), "f"(hi));
    return r;
}
__device__ __forceinline__ void unpack2(u64 v, float &lo, float &hi) {
    asm("mov.b64 {%0, %1}, %2;" : "=f"(lo), "=f"(hi) : "l"(v));
}
#define FMA2(d, a, b, c) \
    asm("fma.rn.f32x2 %0, %1, %2, %3;" : "=l"(d) : "l"(a), "l"(b), "l"(c))

#define SWZ(o) ((o) ^ ((((uint32_t)(o)) >> 3) & 0x70))

#define MMA16816(d, a0, a1, a2, a3, b0, b1)                             \
    asm volatile(                                                       \
        "mma.sync.aligned.m16n8k16.row.col.f32.bf16.bf16.f32 "          \
        "{%0,%1,%2,%3}, {%4,%5,%6,%7}, {%8,%9}, {%0,%1,%2,%3};"         \
        : "+f"((d)[0]), "+f"((d)[1]), "+f"((d)[2]), "+f"((d)[3])        \
        : "r"(a0), "r"(a1), "r"(a2), "r"(a3), "r"(b0), "r"(b1))

#define LDSM4(r0, r1, r2, r3, addr)                                     \
    asm volatile(                                                       \
        "ldmatrix.sync.aligned.m8n8.x4.shared.b16 {%0,%1,%2,%3}, [%4];" \
        : "=r"(r0), "=r"(r1), "=r"(r2), "=r"(r3) : "r"(addr))

__device__ __forceinline__ uint32_t smem_u32(const void *p) {
    uint32_t a;
    asm("{ .reg .u64 t; cvta.to.shared.u64 t, %1; cvt.u32.u64 %0, t; }"
        : "=r"(a) : "l"(p));
    return a;
}

// ---------------------------------------------------------------------------
// Output GEMM via mma.sync bf16 (split precision), ldmatrix fragments.
// THIS ROUND: __launch_bounds__(256, 2) — cap regs at 128 so 2 CTAs/SM
// coexist (round-15 regression hypothesis: reg count pushed it to 1 CTA/SM,
// killing the cross-CTA overlap of the single-buffered pipeline).
// CTA: 128m x 64n, K chunks of 64; 8 warps of 32m x 32n.
// D = Whi.Xhi + Wlo.Xhi + Whi.Xlo (fp32 accumulate).
// ---------------------------------------------------------------------------
__global__ void __launch_bounds__(256, 2) out_gemm_mma(
    const float *__restrict__ W, const float *__restrict__ bias,
    float *__restrict__ Cout) {
    __shared__ __align__(128) __nv_bfloat16 sAhi[128 * 64];
    __shared__ __align__(128) __nv_bfloat16 sAlo[128 * 64];
    __shared__ __align__(128) __nv_bfloat16 sBhi[64 * 64];
    __shared__ __align__(128) __nv_bfloat16 sBlo[64 * 64];

    const int tid = threadIdx.x;
    const int lane = tid & 31;
    const int warp = tid >> 5;
    const int mBase = blockIdx.x * 128;

    const int warpM = (warp & 3) * 32;
    const int warpN = (warp >> 2) * 32;
    const int gid = lane >> 2;   // 0..7
    const int tig = lane & 3;    // 0..3

    const int rowA = tid >> 4;   // 0..15 (+16 per iter, 8 iters)
    const int kq = tid & 15;     // float4 within 64-k chunk
    const int rowB = tid >> 3;   // 0..31 (+32 per iter, 2 iters)
    const int qB = tid & 7;      // uint4 within 128B row

    // ldmatrix per-lane address bases (swizzled row part; kstep XORed in)
    const uint32_t uAhi = smem_u32(sAhi), uAlo = smem_u32(sAlo);
    const uint32_t uBhi = smem_u32(sBhi), uBlo = smem_u32(sBlo);
    const uint32_t kbA = (uint32_t)((lane >> 4) << 4);  // 0 / 16
    const int q2 = lane >> 3, idx8 = lane & 7;
    const uint32_t kbB = (uint32_t)((q2 & 1) << 4);
    uint32_t abase[2], bbase[2];
#pragma unroll
    for (int mt = 0; mt < 2; ++mt)
        abase[mt] = SWZ((uint32_t)((warpM + mt * 16 + (lane & 15)) * 128));
#pragma unroll
    for (int np = 0; np < 2; ++np)
        bbase[np] =
            SWZ((uint32_t)((warpN + (np * 2 + (q2 >> 1)) * 8 + idx8) * 128));

    float acc[2][4][4];
#pragma unroll
    for (int i = 0; i < 2; i++)
#pragma unroll
        for (int j = 0; j < 4; j++)
#pragma unroll
            for (int qq = 0; qq < 4; qq++) acc[i][j][qq] = 0.f;

    for (int c = 0; c < 16; ++c) {
        const int k0 = c * 64;
        // ---- global loads first (in flight across the first sync) ----
        float4 wv[8];
#pragma unroll
        for (int it = 0; it < 8; ++it) {
            int r = rowA + it * 16;
            wv[it] = *(const float4 *)(W + (size_t)(mBase + r) * H + k0 + kq * 4);
        }
        uint4 bh[2], bl[2];
#pragma unroll
        for (int it = 0; it < 2; ++it) {
            int r = rowB + it * 32;
            bh[it] = *(const uint4 *)(g_xhi + (size_t)r * H + k0 + qB * 8);
            bl[it] = *(const uint4 *)(g_xlo + (size_t)r * H + k0 + qB * 8);
        }
        __syncthreads();  // previous chunk fully consumed
        // ---- convert W -> bf16 hi/lo, store swizzled ----
#pragma unroll
        for (int it = 0; it < 8; ++it) {
            int r = rowA + it * 16;
            uint32_t off = SWZ((uint32_t)(r * 128 + kq * 8));
            __nv_bfloat162 h01 = __float22bfloat162_rn(make_float2(wv[it].x, wv[it].y));
            __nv_bfloat162 h23 = __float22bfloat162_rn(make_float2(wv[it].z, wv[it].w));
            float2 f01 = __bfloat1622float2(h01);
            float2 f23 = __bfloat1622float2(h23);
            __nv_bfloat162 l01 = __float22bfloat162_rn(
                make_float2(wv[it].x - f01.x, wv[it].y - f01.y));
            __nv_bfloat162 l23 = __float22bfloat162_rn(
                make_float2(wv[it].z - f23.x, wv[it].w - f23.y));
            *(uint2 *)((char *)sAhi + off) =
                make_uint2(*(uint32_t *)&h01, *(uint32_t *)&h23);
            *(uint2 *)((char *)sAlo + off) =
                make_uint2(*(uint32_t *)&l01, *(uint32_t *)&l23);
        }
#pragma unroll
        for (int it = 0; it < 2; ++it) {
            int r = rowB + it * 32;
            uint32_t off = SWZ((uint32_t)(r * 128 + qB * 16));
            *(uint4 *)((char *)sBhi + off) = bh[it];
            *(uint4 *)((char *)sBlo + off) = bl[it];
        }
        __syncthreads();
        // ---- 4 ksteps of K=16, fragments via ldmatrix ----
#pragma unroll
        for (int ks = 0; ks < 4; ++ks) {
            const uint32_t kb = (uint32_t)(ks * 32);
            uint32_t bhf[8], blf[8];  // [nt*2 + kreg]
            LDSM4(bhf[0], bhf[1], bhf[2], bhf[3], uBhi + (bbase[0] ^ (kb + kbB)));
            LDSM4(bhf[4], bhf[5], bhf[6], bhf[7], uBhi + (bbase[1] ^ (kb + kbB)));
            LDSM4(blf[0], blf[1], blf[2], blf[3], uBlo + (bbase[0] ^ (kb + kbB)));
            LDSM4(blf[4], blf[5], blf[6], blf[7], uBlo + (bbase[1] ^ (kb + kbB)));
#pragma unroll
            for (int mt = 0; mt < 2; ++mt) {
                uint32_t ah[4], al[4];
                LDSM4(ah[0], ah[1], ah[2], ah[3], uAhi + (abase[mt] ^ (kb + kbA)));
                LDSM4(al[0], al[1], al[2], al[3], uAlo + (abase[mt] ^ (kb + kbA)));
#pragma unroll
                for (int nt = 0; nt < 4; ++nt) {
                    MMA16816(acc[mt][nt], ah[0], ah[1], ah[2], ah[3],
                             bhf[nt * 2], bhf[nt * 2 + 1]);
                    MMA16816(acc[mt][nt], al[0], al[1], al[2], al[3],
                             bhf[nt * 2], bhf[nt * 2 + 1]);
                    MMA16816(acc[mt][nt], ah[0], ah[1], ah[2], ah[3],
                             blf[nt * 2], blf[nt * 2 + 1]);
                }
            }
        }
    }

    // ---- epilogue ----
#pragma unroll
    for (int mt = 0; mt < 2; ++mt) {
        int m0 = mBase + warpM + mt * 16 + gid;
        float bv0 = bias[m0], bv1 = bias[m0 + 8];
#pragma unroll
        for (int nt = 0; nt < 4; ++nt) {
            int n0 = warpN + nt * 8 + tig * 2;
            Cout[(size_t)n0 * V + m0]           = acc[mt][nt][0] + bv0;
            Cout[(size_t)(n0 + 1) * V + m0]     = acc[mt][nt][1] + bv0;
            Cout[(size_t)n0 * V + m0 + 8]       = acc[mt][nt][2] + bv1;
            Cout[(size_t)(n0 + 1) * V + m0 + 8] = acc[mt][nt][3] + bv1;
        }
    }
}

// ---------------------------------------------------------------------------
// FMA2 GEMM for the small problems (GRU, concat)
// ---------------------------------------------------------------------------
__global__ void __launch_bounds__(256, 2) gemm128(
    const float *__restrict__ W, const float *__restrict__ X,
    const float *__restrict__ W2, const float *__restrict__ X2,
    const float *__restrict__ bias, float *C, float *C2,
    int M, int K, int kChunk) {
    __shared__ float As[16][128];
    __shared__ float Xd[16][128];
    if (blockIdx.z == 1) { W = W2; X = X2; C = C2; }
    const int tid = threadIdx.x;
    const int mBase = blockIdx.x * 128;
    const int kBase = blockIdx.y * kChunk;
    C += (size_t)blockIdx.y * 64 * M;

    const int ty = tid >> 4;
    const int tx = tid & 15;
    const int lm = tid & 127;
    const int lka = (tid >> 7) << 3;
    const int ln = tid & 63;
    const int lkx = (tid >> 6) << 2;

    const float *Wp = W + (size_t)(mBase + lm) * K + kBase + lka;
    const float *Xp = X + (size_t)ln * K + kBase + lkx;

    float4 wa0 = *(const float4 *)Wp;
    float4 wa1 = *(const float4 *)(Wp + 4);
    float4 xr  = *(const float4 *)Xp;

    u64 acc[4][4];
#pragma unroll
    for (int i = 0; i < 4; i++)
#pragma unroll
        for (int j = 0; j < 4; j++) acc[i][j] = 0ull;

    const int NT = kChunk >> 4;
    for (int kt = 0; kt < NT; ++kt) {
        __syncthreads();
        As[lka + 0][lm] = wa0.x; As[lka + 1][lm] = wa0.y;
        As[lka + 2][lm] = wa0.z; As[lka + 3][lm] = wa0.w;
        As[lka + 4][lm] = wa1.x; As[lka + 5][lm] = wa1.y;
        As[lka + 6][lm] = wa1.z; As[lka + 7][lm] = wa1.w;
        *(u64 *)&Xd[lkx + 0][2 * ln] = pack2(xr.x, xr.x);
        *(u64 *)&Xd[lkx + 1][2 * ln] = pack2(xr.y, xr.y);
        *(u64 *)&Xd[lkx + 2][2 * ln] = pack2(xr.z, xr.z);
        *(u64 *)&Xd[lkx + 3][2 * ln] = pack2(xr.w, xr.w);
        __syncthreads();
        if (kt + 1 < NT) {
            wa0 = *(const float4 *)(Wp + (kt + 1) * 16);
            wa1 = *(const float4 *)(Wp + (kt + 1) * 16 + 4);
            xr  = *(const float4 *)(Xp + (kt + 1) * 16);
        }
#pragma unroll
        for (int k = 0; k < 16; ++k) {
            const ulonglong2 *ar = (const ulonglong2 *)&As[k][ty << 3];
            ulonglong2 a01 = ar[0], a23 = ar[1];
            const ulonglong2 *xp = (const ulonglong2 *)&Xd[k][tx << 3];
            ulonglong2 x01 = xp[0], x23 = xp[1];
            FMA2(acc[0][0], a01.x, x01.x, acc[0][0]);
            FMA2(acc[0][1], a01.x, x01.y, acc[0][1]);
            FMA2(acc[0][2], a01.x, x23.x, acc[0][2]);
            FMA2(acc[0][3], a01.x, x23.y, acc[0][3]);
            FMA2(acc[1][0], a01.y, x01.x, acc[1][0]);
            FMA2(acc[1][1], a01.y, x01.y, acc[1][1]);
            FMA2(acc[1][2], a01.y, x23.x, acc[1][2]);
            FMA2(acc[1][3], a01.y, x23.y, acc[1][3]);
            FMA2(acc[2][0], a23.x, x01.x, acc[2][0]);
            FMA2(acc[2][1], a23.x, x01.y, acc[2][1]);
            FMA2(acc[2][2], a23.x, x23.x, acc[2][2]);
            FMA2(acc[2][3], a23.x, x23.y, acc[2][3]);
            FMA2(acc[3][0], a23.y, x01.x, acc[3][0]);
            FMA2(acc[3][1], a23.y, x01.y, acc[3][1]);
            FMA2(acc[3][2], a23.y, x23.x, acc[3][2]);
            FMA2(acc[3][3], a23.y, x23.y, acc[3][3]);
        }
    }

    float cv[8][4];
#pragma unroll
    for (int mp = 0; mp < 4; mp++)
#pragma unroll
        for (int nj = 0; nj < 4; nj++)
            unpack2(acc[mp][nj], cv[mp * 2][nj], cv[mp * 2 + 1][nj]);

    float bb[8];
    if (bias) {
        float4 b0 = *(const float4 *)(bias + mBase + (ty << 3));
        float4 b1 = *(const float4 *)(bias + mBase + (ty << 3) + 4);
        bb[0] = b0.x; bb[1] = b0.y; bb[2] = b0.z; bb[3] = b0.w;
        bb[4] = b1.x; bb[5] = b1.y; bb[6] = b1.z; bb[7] = b1.w;
    } else {
#pragma unroll
        for (int i = 0; i < 8; i++) bb[i] = 0.f;
    }
#pragma unroll
    for (int nj = 0; nj < 4; nj++) {
        float *cp = C + (size_t)((tx << 2) + nj) * M + mBase + (ty << 3);
        float4 v0 = make_float4(cv[0][nj] + bb[0], cv[1][nj] + bb[1],
                                cv[2][nj] + bb[2], cv[3][nj] + bb[3]);
        float4 v1 = make_float4(cv[4][nj] + bb[4], cv[5][nj] + bb[5],
                                cv[6][nj] + bb[6], cv[7][nj] + bb[7]);
        *(float4 *)cp = v0;
        *(float4 *)(cp + 4) = v1;
    }
}

// ---------------------------------------------------------------------------
__global__ void __launch_bounds__(256) gather_emb(
    const int *__restrict__ seq, const float *__restrict__ emb_table) {
    int idx = blockIdx.x * 256 + threadIdx.x;
    int b = idx >> 8;
    int h4 = (idx & 255) << 2;
    int row = seq[b];
    *(float4 *)(g_emb + b * H + h4) =
        *(const float4 *)(emb_table + (size_t)row * H + h4);
}

// ---------------------------------------------------------------------------
__global__ void __launch_bounds__(256) gru_combine(
    const float *__restrict__ hprev, const float *__restrict__ b_ih,
    const float *__restrict__ b_hh, float *__restrict__ out_hidden) {
    int idx = blockIdx.x * 256 + threadIdx.x;
    int b = idx >> 8;
    int h4 = (idx & 255) << 2;

    float4 gx[3], gh[3];
#pragma unroll
    for (int g = 0; g < 3; g++) {
        gx[g] = *(const float4 *)(b_ih + g * H + h4);
        gh[g] = *(const float4 *)(b_hh + g * H + h4);
#pragma unroll
        for (int s = 0; s < S_GRU; s++) {
            size_t off = ((size_t)s * B + b) * 3 * H + g * H + h4;
            float4 px = *(const float4 *)(g_gxp + off);
            float4 ph = *(const float4 *)(g_ghp + off);
            gx[g].x += px.x; gx[g].y += px.y; gx[g].z += px.z; gx[g].w += px.w;
            gh[g].x += ph.x; gh[g].y += ph.y; gh[g].z += ph.z; gh[g].w += ph.w;
        }
    }
    float4 hp = *(const float4 *)(hprev + b * H + h4);
    float4 ho;
#pragma unroll
    for (int j = 0; j < 4; j++) {
        float xr = (&gx[0].x)[j], xz = (&gx[1].x)[j], xn = (&gx[2].x)[j];
        float hr = (&gh[0].x)[j], hz = (&gh[1].x)[j], hn = (&gh[2].x)[j];
        float r = 1.f / (1.f + expf(-(xr + hr)));
        float z = 1.f / (1.f + expf(-(xz + hz)));
        float n = tanhf(xn + r * hn);
        (&ho.x)[j] = (1.f - z) * n + z * (&hp.x)[j];
    }
    *(float4 *)(g_hnew + b * H + h4) = ho;
    *(float4 *)(out_hidden + b * H + h4) = ho;
    *(float4 *)(g_concat_in + b * 2 * H + h4) = ho;
}

// ---------------------------------------------------------------------------
// Fused attention pass 1: 256 timesteps per CTA (8 blocks of 32).
// ---------------------------------------------------------------------------
__global__ void __launch_bounds__(256, 2) attn_partial(const float *__restrict__ enc) {
    const int b = blockIdx.y;
    const int chunk = blockIdx.x;
    const int t0 = chunk * 256;
    const int tid = threadIdx.x;
    const int warp = tid >> 5, lane = tid & 31;

    __shared__ float sblk[32];
    __shared__ float eblk[32];

    const float *hb = g_hnew + b * H + lane * 4;
    ulonglong2 hv[8];
#pragma unroll
    for (int i = 0; i < 8; i++) hv[i] = *(const ulonglong2 *)(hb + i * 128);

    float M = -1e30f, S = 0.f;
    float4 cacc = make_float4(0.f, 0.f, 0.f, 0.f);
    const float *ebase = enc + ((size_t)t0 * B + b) * H;

    for (int blk = 0; blk < 8; blk++) {
        const int tb = blk * 32;
        float sq[4];
#pragma unroll
        for (int q = 0; q < 4; q++) {
            const int tl = tb + warp * 4 + q;
            const float *e = ebase + (size_t)tl * B * H + lane * 4;
            u64 acc = 0ull;
#pragma unroll
            for (int i = 0; i < 8; i++) {
                ulonglong2 ev = *(const ulonglong2 *)(e + i * 128);
                FMA2(acc, ev.x, hv[i].x, acc);
                FMA2(acc, ev.y, hv[i].y, acc);
            }
            float lo, hi;
            unpack2(acc, lo, hi);
            float s = lo + hi;
#pragma unroll
            for (int o = 16; o; o >>= 1) s += __shfl_xor_sync(0xffffffffu, s, o);
            sq[q] = s;
            if (!lane) g_scores[b * T + t0 + tl] = s;
        }
        if (!lane) {
            sblk[warp * 4 + 0] = sq[0]; sblk[warp * 4 + 1] = sq[1];
            sblk[warp * 4 + 2] = sq[2]; sblk[warp * 4 + 3] = sq[3];
        }
        __syncthreads();
        float m_blk = sblk[0];
#pragma unroll
        for (int i = 1; i < 32; i++) m_blk = fmaxf(m_blk, sblk[i]);
        float Mn = fmaxf(M, m_blk);
        float r = expf(M - Mn);
        if (tid < 32) eblk[tid] = expf(sblk[tid] - Mn);
        __syncthreads();
        float es = 0.f;
#pragma unroll
        for (int i = 0; i < 32; i++) es += eblk[i];
        S = S * r + es;
        M = Mn;
        cacc.x *= r; cacc.y *= r; cacc.z *= r; cacc.w *= r;
        const float *e2 = ebase + (size_t)tb * B * H + tid * 4;
#pragma unroll 8
        for (int t = 0; t < 32; t++) {
            float w = eblk[t];
            float4 ev = *(const float4 *)(e2 + (size_t)t * B * H);
            cacc.x += w * ev.x; cacc.y += w * ev.y;
            cacc.z += w * ev.z; cacc.w += w * ev.w;
        }
        __syncthreads();
    }

    *(float4 *)(g_ctxpart + ((size_t)b * NCHUNK + chunk) * H + tid * 4) = cacc;
    if (tid == 0) {
        g_pm[b * NCHUNK + chunk] = M;
        g_ps[b * NCHUNK + chunk] = S;
    }
}

// ---------------------------------------------------------------------------
__global__ void __launch_bounds__(256) attn_combine(float *__restrict__ attn_out) {
    const int b = blockIdx.x;
    const int tid = threadIdx.x;

    float m[NCHUNK], s[NCHUNK];
#pragma unroll
    for (int j = 0; j < NCHUNK; j++) {
        m[j] = g_pm[b * NCHUNK + j];
        s[j] = g_ps[b * NCHUNK + j];
    }
    float gm = m[0];
#pragma unroll
    for (int j = 1; j < NCHUNK; j++) gm = fmaxf(gm, m[j]);
    float gsum = 0.f;
    float f[NCHUNK];
#pragma unroll
    for (int j = 0; j < NCHUNK; j++) {
        f[j] = expf(m[j] - gm);
        gsum += f[j] * s[j];
    }
    float inv = 1.f / gsum;

    int h4 = tid * 4;
    float4 c = make_float4(0.f, 0.f, 0.f, 0.f);
#pragma unroll
    for (int j = 0; j < NCHUNK; j++) {
        float4 p = *(const float4 *)(g_ctxpart + ((size_t)b * NCHUNK + j) * H + h4);
        float fj = f[j] * inv;
        c.x += fj * p.x; c.y += fj * p.y; c.z += fj * p.z; c.w += fj * p.w;
    }
    *(float4 *)(g_concat_in + b * 2 * H + H + h4) = c;

    float4 sc = *(const float4 *)(g_scores + b * T + tid * 4);
    float4 a = make_float4(expf(sc.x - gm) * inv, expf(sc.y - gm) * inv,
                           expf(sc.z - gm) * inv, expf(sc.w - gm) * inv);
    *(float4 *)(attn_out + b * T + tid * 4) = a;
}

// ---------------------------------------------------------------------------
// Concat reduce: split-K sum + bias + tanh, emit bf16 hi/lo directly.
// ---------------------------------------------------------------------------
__global__ void __launch_bounds__(256) concat_reduce(const float *__restrict__ cb) {
    int idx = blockIdx.x * 256 + threadIdx.x;  // B*H/4
    int b = idx >> 8;
    int h4 = (idx & 255) << 2;
    float4 s = *(const float4 *)(cb + h4);
#pragma unroll
    for (int j = 0; j < S_CAT; j++) {
        float4 p = *(const float4 *)(g_cp + ((size_t)j * B + b) * H + h4);
        s.x += p.x; s.y += p.y; s.z += p.z; s.w += p.w;
    }
    s.x = tanhf(s.x); s.y = tanhf(s.y); s.z = tanhf(s.z); s.w = tanhf(s.w);

    __nv_bfloat162 h01 = __float22bfloat162_rn(make_float2(s.x, s.y));
    __nv_bfloat162 h23 = __float22bfloat162_rn(make_float2(s.z, s.w));
    float2 f01 = __bfloat1622float2(h01);
    float2 f23 = __bfloat1622float2(h23);
    __nv_bfloat162 l01 = __float22bfloat162_rn(make_float2(s.x - f01.x, s.y - f01.y));
    __nv_bfloat162 l23 = __float22bfloat162_rn(make_float2(s.z - f23.x, s.w - f23.y));
    size_t o = (size_t)b * H + h4;
    *(uint2 *)(g_xhi + o) = make_uint2(*(uint32_t *)&h01, *(uint32_t *)&h23);
    *(uint2 *)(g_xlo + o) = make_uint2(*(uint32_t *)&l01, *(uint32_t *)&l23);
}

// ---------------------------------------------------------------------------
extern "C" void kernel_launch(void *const *d_in, const int *in_sizes, int n_in,
                              void *d_out, int out_size) {
    const int *seq     = (const int *)d_in[0];
    const float *hprev = (const float *)d_in[1];
    const float *enc   = (const float *)d_in[2];
    const float *emb   = (const float *)d_in[3];
    const float *w_ih  = (const float *)d_in[4];
    const float *w_hh  = (const float *)d_in[5];
    const float *b_ih  = (const float *)d_in[6];
    const float *b_hh  = (const float *)d_in[7];
    const float *cW    = (const float *)d_in[8];
    const float *cb    = (const float *)d_in[9];
    const float *oW    = (const float *)d_in[10];
    const float *ob    = (const float *)d_in[11];
    float *out = (float *)d_out;

    float *p_emb, *p_gxp, *p_ghp, *p_cin, *p_cp;
    cudaGetSymbolAddress((void **)&p_emb,  g_emb);
    cudaGetSymbolAddress((void **)&p_gxp,  g_gxp);
    cudaGetSymbolAddress((void **)&p_ghp,  g_ghp);
    cudaGetSymbolAddress((void **)&p_cin,  g_concat_in);
    cudaGetSymbolAddress((void **)&p_cp,   g_cp);

    float *out_hidden = out + (size_t)B * V;
    float *out_attn   = out + (size_t)B * V + (size_t)B * H;

    // 1) embedding gather
    gather_emb<<<64, 256>>>(seq, emb);
    // 2) both GRU GEMMs fused, split-K=4
    gemm128<<<dim3(3 * H / 128, S_GRU, 2), 256>>>(
        w_ih, p_emb, w_hh, hprev, nullptr, p_gxp, p_ghp, 3 * H, H, H / S_GRU);
    // 3) gate combine
    gru_combine<<<64, 256>>>(hprev, b_ih, b_hh, out_hidden);
    // 4) fused attention (4 chunks x 64 b = 256 CTAs)
    attn_partial<<<dim3(NCHUNK, B), 256>>>(enc);
    attn_combine<<<B, 256>>>(out_attn);
    // 5) concat GEMM split-K=16; reduce fuses bias+tanh+bf16 conversion
    gemm128<<<dim3(H / 128, S_CAT, 1), 256>>>(
        cW, p_cin, cW, p_cin, nullptr, p_cp, p_cp, H, 2 * H, 2 * H / S_CAT);
    concat_reduce<<<64, 256>>>(cb);
    // 6) output GEMM on mma.sync bf16 (ldmatrix fragments, 2 CTAs/SM)
    out_gemm_mma<<<V / 128, 256>>>(oW, ob, out);
}